// round 7
// baseline (speedup 1.0000x reference)
#include <cuda_runtime.h>
#include <cuda_fp16.h>
#include <math.h>

#define DIMZ 128
#define HW   (128*128)
#define VOL  (128*128*128)
#define NB   2
#define NK   4
#define RAD  4
#define ZC   16                 // z-chunk in K2
#define K2_CTAS (16*8*8)        // ytiles * zchunks * (k*b)

// fp16 scratch: XY-blurred labels field + fp16 copy of labels (64 MB total,
// L2-resident between K1 and K2).
__device__ __align__(16) __half g_blur[NB*NK*VOL];
__device__ __align__(16) __half g_lab [NB*NK*VOL];

struct Scal {
    float  S1[NB*NK];
    float  S2[NB*NK];
    double num[NK];
    double den[NK];
    int    ctr;
};
__device__ Scal g_s;

// gauss taps: exp(-x^2/(2*25)) for x=-4..4 (fp32, for x-blur)
__constant__ float c_g[9] = {
    0.72614904f, 0.83527021f, 0.92311635f, 0.98019867f, 1.0f,
    0.98019867f, 0.92311635f, 0.83527021f, 0.72614904f
};
// same taps as packed half2 bit patterns (round-to-nearest fp16)
__constant__ unsigned c_gh2[9] = {
    0x39CF39CFu, 0x3AAF3AAFu, 0x3B633B63u, 0x3BD73BD7u, 0x3C003C00u,
    0x3BD73BD7u, 0x3B633B63u, 0x3AAF3AAFu, 0x39CF39CFu
};

__device__ __forceinline__ __half2 u2h(unsigned u) {
    return *reinterpret_cast<__half2*>(&u);
}
__device__ __forceinline__ unsigned h2u(__half2 h) {
    return *reinterpret_cast<unsigned*>(&h);
}

__device__ __forceinline__ float blur9(const float* a) {
    float acc = 0.f;
    #pragma unroll
    for (int t = 0; t < 9; t++) acc = fmaf(c_g[t], a[t], acc);
    return acc;
}

__device__ __forceinline__ uint2 packf4(float4 r) {
    uint2 p;
    p.x = h2u(__floats2half2_rn(r.x, r.y));
    p.y = h2u(__floats2half2_rn(r.z, r.w));
    return p;
}

// Load labels row gy (zero outside volume). On uniquely-owned center rows:
// accumulate mean sums AND store a packed fp16 copy of the labels (consumed
// by K2 from L2). Returns the X-blurred float4 for this lane (x = 4*lane),
// halo via lane shuffles. No shared memory.
__device__ __forceinline__ float4 xblur_load(
    int gy, const float4* __restrict__ lp4, const float4* __restrict__ ip4,
    __half* __restrict__ lab_op,
    int lane, int y0, float& s1, float& s2)
{
    float4 c = make_float4(0.f, 0.f, 0.f, 0.f);
    if (gy >= 0 && gy < 128) {
        c = __ldcs(lp4 + gy * 32 + lane);
        if (gy >= y0 && gy < y0 + 32) {
            float4 u = ip4[gy * 32 + lane];
            s1 += c.x*u.x + c.y*u.y + c.z*u.z + c.w*u.w;
            s2 += c.x + c.y + c.z + c.w;
            *reinterpret_cast<uint2*>(lab_op + gy * 128 + lane * 4) = packf4(c);
        }
    }
    float a[12];
    a[0] = __shfl_up_sync(0xffffffffu, c.x, 1);
    a[1] = __shfl_up_sync(0xffffffffu, c.y, 1);
    a[2] = __shfl_up_sync(0xffffffffu, c.z, 1);
    a[3] = __shfl_up_sync(0xffffffffu, c.w, 1);
    if (lane == 0) { a[0] = a[1] = a[2] = a[3] = 0.f; }
    a[4] = c.x; a[5] = c.y; a[6] = c.z; a[7] = c.w;
    a[8]  = __shfl_down_sync(0xffffffffu, c.x, 1);
    a[9]  = __shfl_down_sync(0xffffffffu, c.y, 1);
    a[10] = __shfl_down_sync(0xffffffffu, c.z, 1);
    a[11] = __shfl_down_sync(0xffffffffu, c.w, 1);
    if (lane == 31) { a[8] = a[9] = a[10] = a[11] = 0.f; }
    float4 r;
    r.x = blur9(a + 0);
    r.y = blur9(a + 1);
    r.z = blur9(a + 2);
    r.w = blur9(a + 3);
    return r;
}

// ---------------------------------------------------------------------------
// K1: XY blur of labels, register/shuffle resident; y-ring packed half2,
// y-blur in HFMA2. Also emits fp16 labels copy + per-(b,k) mean sums.
// grid: (64 zpairs, 4 k, 2 b) x 256 thr; warp w -> z = 2*zg + (w>>2), yq = w&3.
// ---------------------------------------------------------------------------
__global__ __launch_bounds__(256)
void k_xyblur(const float* __restrict__ labels, const float* __restrict__ inputs) {
    const int tid = threadIdx.x;
    const int warp = tid >> 5, lane = tid & 31;
    const int z  = blockIdx.x * 2 + (warp >> 2);
    const int yq = warp & 3;
    const int y0 = yq * 32;
    const int k  = blockIdx.y;
    const int b  = blockIdx.z;
    const int x4 = lane * 4;

    const size_t slab = (size_t)(b*NK + k) * VOL + (size_t)z * HW;
    const float4* lp4 = (const float4*)(labels + slab);
    const float4* ip4 = (const float4*)(inputs + (size_t)b * VOL + (size_t)z * HW);
    __half* op     = g_blur + slab;
    __half* lab_op = g_lab  + slab;

    float s1 = 0.f, s2 = 0.f;
    uint2 w[9];
    #pragma unroll
    for (int j = 0; j < 9; j++)
        w[j] = packf4(xblur_load(y0 - RAD + j, lp4, ip4, lab_op, lane, y0, s1, s2));

    #pragma unroll 4
    for (int i = 0; i < 32; i++) {
        __half2 b0 = u2h(0u), b1 = u2h(0u);
        #pragma unroll
        for (int j = 0; j < 9; j++) {
            __half2 g = u2h(c_gh2[j]);
            b0 = __hfma2(g, u2h(w[j].x), b0);
            b1 = __hfma2(g, u2h(w[j].y), b1);
        }
        uint2 pk; pk.x = h2u(b0); pk.y = h2u(b1);
        *reinterpret_cast<uint2*>(op + (y0 + i) * 128 + x4) = pk;

        #pragma unroll
        for (int j = 0; j < 8; j++) w[j] = w[j + 1];
        w[8] = packf4(xblur_load(y0 + i + RAD + 1, lp4, ip4, lab_op, lane, y0, s1, s2));
    }

    // Warp-reduce mean sums, then CTA-reduce -> 2 atomics per CTA.
    #pragma unroll
    for (int o = 16; o; o >>= 1) {
        s1 += __shfl_down_sync(0xffffffffu, s1, o);
        s2 += __shfl_down_sync(0xffffffffu, s2, o);
    }
    __shared__ float rs1[8], rs2[8];
    if (lane == 0) { rs1[warp] = s1; rs2[warp] = s2; }
    __syncthreads();
    if (tid == 0) {
        float a = 0.f, c = 0.f;
        #pragma unroll
        for (int ww = 0; ww < 8; ww++) { a += rs1[ww]; c += rs2[ww]; }
        atomicAdd(&g_s.S1[b*NK + k], a);
        atomicAdd(&g_s.S2[b*NK + k], c);
    }
}

// ---------------------------------------------------------------------------
// K2: Z blur with rolling half2 window (HFMA2), fused weights + reduction.
//     num = sum B(p)*p*w,  den = sum B(p)*w   (blur operator self-adjoint).
// Reads ONLY fp16 scratch (L2-resident) + inputs. No fp32 labels stream.
// grid: (16 ytiles, 8 zchunks, 8 = k + 4*b) x 256. Last CTA finalizes.
// ---------------------------------------------------------------------------
__global__ __launch_bounds__(256, 5)
void k_zred(const float* __restrict__ inputs, float* __restrict__ out) {
    const int tid  = threadIdx.x;
    const int warp = tid >> 5, lane = tid & 31;
    const int y  = blockIdx.x * 8 + warp;
    const int z0 = blockIdx.y * ZC;
    const int k  = blockIdx.z & 3;
    const int b  = blockIdx.z >> 2;
    const int bk = b*NK + k;
    const int x4 = lane * 4;

    const float Nf = (float)VOL;
    const float mean = (g_s.S1[bk] / Nf) / (g_s.S2[bk] / Nf + 1e-5f);

    const __half*  bp = g_blur + (size_t)bk * VOL + y * 128 + x4;
    const __half*  hp = g_lab  + (size_t)bk * VOL + y * 128 + x4;
    const float4*  ip = (const float4*)(inputs + (size_t)b * VOL + y * 128 + x4);

    uint2 v[9];
    #pragma unroll
    for (int j = 0; j < 9; j++) {
        int zz = z0 - RAD + j;
        v[j] = (zz >= 0 && zz < DIMZ)
             ? *reinterpret_cast<const uint2*>(bp + (size_t)zz * HW)
             : make_uint2(0u, 0u);
    }

    float num = 0.f, den = 0.f;

    #pragma unroll 2
    for (int cz = 0; cz < ZC; cz++) {
        int z = z0 + cz;
        __half2 b0 = u2h(0u), b1 = u2h(0u);
        #pragma unroll
        for (int j = 0; j < 9; j++) {
            __half2 g = u2h(c_gh2[j]);
            b0 = __hfma2(g, u2h(v[j].x), b0);
            b1 = __hfma2(g, u2h(v[j].y), b1);
        }
        float2 f0 = __half22float2(b0);
        float2 f1 = __half22float2(b1);

        uint2 lu = *reinterpret_cast<const uint2*>(hp + (size_t)z * HW);
        float2 l0 = __half22float2(u2h(lu.x));
        float2 l1 = __half22float2(u2h(lu.y));
        float4 inp = ip[(size_t)z * (HW/4)];

        {
            float d = inp.x - mean, d2 = d*d, wv = __expf(-d2*d2);
            num = fmaf(f0.x * l0.x, wv, num); den = fmaf(f0.x, wv, den);
        }
        {
            float d = inp.y - mean, d2 = d*d, wv = __expf(-d2*d2);
            num = fmaf(f0.y * l0.y, wv, num); den = fmaf(f0.y, wv, den);
        }
        {
            float d = inp.z - mean, d2 = d*d, wv = __expf(-d2*d2);
            num = fmaf(f1.x * l1.x, wv, num); den = fmaf(f1.x, wv, den);
        }
        {
            float d = inp.w - mean, d2 = d*d, wv = __expf(-d2*d2);
            num = fmaf(f1.y * l1.y, wv, num); den = fmaf(f1.y, wv, den);
        }

        #pragma unroll
        for (int j = 0; j < 8; j++) v[j] = v[j + 1];
        int zn = z + RAD + 1;
        v[8] = (zn < DIMZ)
             ? *reinterpret_cast<const uint2*>(bp + (size_t)zn * HW)
             : make_uint2(0u, 0u);
    }

    // CTA reduction -> 2 double atomics.
    #pragma unroll
    for (int o = 16; o; o >>= 1) {
        num += __shfl_down_sync(0xffffffffu, num, o);
        den += __shfl_down_sync(0xffffffffu, den, o);
    }
    __shared__ float rn[8], rd[8];
    if (lane == 0) { rn[warp] = num; rd[warp] = den; }
    __syncthreads();
    __shared__ bool is_last;
    if (tid == 0) {
        double a = 0.0, c = 0.0;
        #pragma unroll
        for (int w = 0; w < 8; w++) { a += (double)rn[w]; c += (double)rd[w]; }
        atomicAdd(&g_s.num[k], a);
        atomicAdd(&g_s.den[k], c);
        __threadfence();
        int done = atomicAdd(&g_s.ctr, 1);
        is_last = (done == K2_CTAS - 1);
    }
    __syncthreads();

    if (is_last && tid == 0) {
        __threadfence();
        float loss = 0.f;
        #pragma unroll
        for (int kk = 0; kk < NK; kk++) {
            float n = (float)g_s.num[kk];
            float d = (float)g_s.den[kk];
            loss += fabsf(n / (d + 1e-6f));
        }
        out[0] = (float)NK - loss;
    }
}

extern "C" void kernel_launch(void* const* d_in, const int* in_sizes, int n_in,
                              void* d_out, int out_size) {
    const float* labels;
    const float* inputs;
    if (in_sizes[0] == NB*NK*VOL) {
        labels = (const float*)d_in[0];
        inputs = (const float*)d_in[1];
    } else {
        labels = (const float*)d_in[1];
        inputs = (const float*)d_in[0];
    }

    void* scal_ptr = nullptr;
    cudaGetSymbolAddress(&scal_ptr, g_s);
    cudaMemsetAsync(scal_ptr, 0, sizeof(Scal));

    dim3 g1(64, 4, 2);
    k_xyblur<<<g1, 256>>>(labels, inputs);

    dim3 g2(16, 8, 8);
    k_zred<<<g2, 256>>>(inputs, (float*)d_out);
}

// round 8
// speedup vs baseline: 1.0019x; 1.0019x over previous
#include <cuda_runtime.h>
#include <cuda_fp16.h>
#include <math.h>

#define DIMZ 128
#define HW   (128*128)
#define VOL  (128*128*128)
#define NB   2
#define NK   4
#define RAD  4
#define ZC   16                 // z-chunk in K2
#define K2_CTAS (16*8*8)        // ytiles * zchunks * (k*b)

// 32 MB fp16 scratch for the XY-blurred labels field (L2-resident for K2).
__device__ __align__(16) __half g_blur[NB*NK*VOL];

struct Scal {
    float  S1[NB*NK];
    float  S2[NB*NK];
    double num[NK];
    double den[NK];
    int    ctr;
};
__device__ Scal g_s;

// gauss taps: exp(-x^2/(2*25)) for x=-4..4 (fp32; symmetric)
__constant__ float c_g[5] = {  // c_g[j] = tap |j-4|
    0.72614904f, 0.83527021f, 0.92311635f, 0.98019867f, 1.0f
};
// taps 0..4 as packed half2 (round-to-nearest fp16)
__constant__ unsigned c_gh2[5] = {
    0x39CF39CFu, 0x3AAF3AAFu, 0x3B633B63u, 0x3BD73BD7u, 0x3C003C00u
};

__device__ __forceinline__ __half2 u2h(unsigned u) {
    return *reinterpret_cast<__half2*>(&u);
}
__device__ __forceinline__ unsigned h2u(__half2 h) {
    return *reinterpret_cast<unsigned*>(&h);
}

// Symmetric 9-tap blur over a[0..8+off]: pairs reduce the serial-FMA depth.
__device__ __forceinline__ float blur9s(const float* a) {
    float p0 = a[0] + a[8];
    float p1 = a[1] + a[7];
    float p2 = a[2] + a[6];
    float p3 = a[3] + a[5];
    float acc = c_g[4] * a[4];
    acc = fmaf(c_g[0], p0, acc);
    acc = fmaf(c_g[1], p1, acc);
    acc = fmaf(c_g[2], p2, acc);
    acc = fmaf(c_g[3], p3, acc);
    return acc;
}

__device__ __forceinline__ uint2 packf4(float4 r) {
    uint2 p;
    p.x = h2u(__floats2half2_rn(r.x, r.y));
    p.y = h2u(__floats2half2_rn(r.z, r.w));
    return p;
}

// Load labels row gy with x-halo via 3 overlapping float4 loads (no shuffles),
// zero outside the volume / row edges. Accumulates mean sums on the uniquely
// owned center rows. Returns the X-blurred float4 for this lane (x = 4*lane).
__device__ __forceinline__ float4 xblur_load(
    int gy, const float4* __restrict__ lp4, const float4* __restrict__ ip4,
    int lane, int y0, float& s1, float& s2)
{
    float4 c = make_float4(0.f, 0.f, 0.f, 0.f);
    float4 l = c, r = c;
    if (gy >= 0 && gy < 128) {
        const float4* row = lp4 + gy * 32;
        c = __ldcs(row + lane);
        if (lane > 0)  l = __ldcs(row + lane - 1);
        if (lane < 31) r = __ldcs(row + lane + 1);
        if (gy >= y0 && gy < y0 + 32) {
            float4 u = ip4[gy * 32 + lane];
            s1 += c.x*u.x + c.y*u.y + c.z*u.z + c.w*u.w;
            s2 += c.x + c.y + c.z + c.w;
        }
    }
    float a[12];
    a[0] = l.x; a[1] = l.y; a[2]  = l.z; a[3]  = l.w;
    a[4] = c.x; a[5] = c.y; a[6]  = c.z; a[7]  = c.w;
    a[8] = r.x; a[9] = r.y; a[10] = r.z; a[11] = r.w;
    float4 o;
    o.x = blur9s(a + 0);
    o.y = blur9s(a + 1);
    o.z = blur9s(a + 2);
    o.w = blur9s(a + 3);
    return o;
}

// ---------------------------------------------------------------------------
// K1: XY blur of labels, register-resident; x-halo from gmem (L1 hits),
// y-ring packed half2 with symmetric HADD2/HFMA2 taps.
// grid: (64 zpairs, 4 k, 2 b) x 256 thr; warp w -> z = 2*zg + (w>>2), yq = w&3.
// Fused: per-(b,k) mean sums.
// ---------------------------------------------------------------------------
__global__ __launch_bounds__(256, 5)
void k_xyblur(const float* __restrict__ labels, const float* __restrict__ inputs) {
    const int tid = threadIdx.x;
    const int warp = tid >> 5, lane = tid & 31;
    const int z  = blockIdx.x * 2 + (warp >> 2);
    const int yq = warp & 3;
    const int y0 = yq * 32;
    const int k  = blockIdx.y;
    const int b  = blockIdx.z;
    const int x4 = lane * 4;

    const size_t slab = (size_t)(b*NK + k) * VOL + (size_t)z * HW;
    const float4* lp4 = (const float4*)(labels + slab);
    const float4* ip4 = (const float4*)(inputs + (size_t)b * VOL + (size_t)z * HW);
    __half* op = g_blur + slab;

    float s1 = 0.f, s2 = 0.f;
    uint2 w[9];
    #pragma unroll
    for (int j = 0; j < 9; j++)
        w[j] = packf4(xblur_load(y0 - RAD + j, lp4, ip4, lane, y0, s1, s2));

    #pragma unroll 2
    for (int i = 0; i < 32; i++) {
        // symmetric y-taps in half2
        __half2 p0a = __hadd2(u2h(w[0].x), u2h(w[8].x));
        __half2 p1a = __hadd2(u2h(w[1].x), u2h(w[7].x));
        __half2 p2a = __hadd2(u2h(w[2].x), u2h(w[6].x));
        __half2 p3a = __hadd2(u2h(w[3].x), u2h(w[5].x));
        __half2 b0  = __hmul2(u2h(c_gh2[4]), u2h(w[4].x));
        b0 = __hfma2(u2h(c_gh2[0]), p0a, b0);
        b0 = __hfma2(u2h(c_gh2[1]), p1a, b0);
        b0 = __hfma2(u2h(c_gh2[2]), p2a, b0);
        b0 = __hfma2(u2h(c_gh2[3]), p3a, b0);

        __half2 p0b = __hadd2(u2h(w[0].y), u2h(w[8].y));
        __half2 p1b = __hadd2(u2h(w[1].y), u2h(w[7].y));
        __half2 p2b = __hadd2(u2h(w[2].y), u2h(w[6].y));
        __half2 p3b = __hadd2(u2h(w[3].y), u2h(w[5].y));
        __half2 b1  = __hmul2(u2h(c_gh2[4]), u2h(w[4].y));
        b1 = __hfma2(u2h(c_gh2[0]), p0b, b1);
        b1 = __hfma2(u2h(c_gh2[1]), p1b, b1);
        b1 = __hfma2(u2h(c_gh2[2]), p2b, b1);
        b1 = __hfma2(u2h(c_gh2[3]), p3b, b1);

        uint2 pk; pk.x = h2u(b0); pk.y = h2u(b1);
        *reinterpret_cast<uint2*>(op + (y0 + i) * 128 + x4) = pk;

        #pragma unroll
        for (int j = 0; j < 8; j++) w[j] = w[j + 1];
        w[8] = packf4(xblur_load(y0 + i + RAD + 1, lp4, ip4, lane, y0, s1, s2));
    }

    // Warp-reduce mean sums, then CTA-reduce -> 2 atomics per CTA.
    #pragma unroll
    for (int o = 16; o; o >>= 1) {
        s1 += __shfl_down_sync(0xffffffffu, s1, o);
        s2 += __shfl_down_sync(0xffffffffu, s2, o);
    }
    __shared__ float rs1[8], rs2[8];
    if (lane == 0) { rs1[warp] = s1; rs2[warp] = s2; }
    __syncthreads();
    if (tid == 0) {
        float a = 0.f, c = 0.f;
        #pragma unroll
        for (int ww = 0; ww < 8; ww++) { a += rs1[ww]; c += rs2[ww]; }
        atomicAdd(&g_s.S1[b*NK + k], a);
        atomicAdd(&g_s.S2[b*NK + k], c);
    }
}

// ---------------------------------------------------------------------------
// K2: Z blur with rolling half2 window (symmetric taps), fused weights +
// reduction. num = sum B(p)*p*w, den = sum B(p)*w (blur self-adjoint).
// labels fp32 streamed from DRAM (__ldcs), blur fp16 from L2 scratch.
// grid: (16 ytiles, 8 zchunks, 8 = k + 4*b) x 256. Last CTA finalizes.
// ---------------------------------------------------------------------------
__global__ __launch_bounds__(256, 5)
void k_zred(const float* __restrict__ labels, const float* __restrict__ inputs,
            float* __restrict__ out) {
    const int tid  = threadIdx.x;
    const int warp = tid >> 5, lane = tid & 31;
    const int y  = blockIdx.x * 8 + warp;
    const int z0 = blockIdx.y * ZC;
    const int k  = blockIdx.z & 3;
    const int b  = blockIdx.z >> 2;
    const int bk = b*NK + k;
    const int x4 = lane * 4;

    const float Nf = (float)VOL;
    const float mean = (g_s.S1[bk] / Nf) / (g_s.S2[bk] / Nf + 1e-5f);

    const __half*  bp = g_blur + (size_t)bk * VOL + y * 128 + x4;
    const float4*  lp = (const float4*)(labels + (size_t)bk * VOL + y * 128 + x4);
    const float4*  ip = (const float4*)(inputs + (size_t)b  * VOL + y * 128 + x4);

    uint2 v[9];
    #pragma unroll
    for (int j = 0; j < 9; j++) {
        int zz = z0 - RAD + j;
        v[j] = (zz >= 0 && zz < DIMZ)
             ? *reinterpret_cast<const uint2*>(bp + (size_t)zz * HW)
             : make_uint2(0u, 0u);
    }

    float num = 0.f, den = 0.f;

    #pragma unroll 2
    for (int cz = 0; cz < ZC; cz++) {
        int z = z0 + cz;

        __half2 p0a = __hadd2(u2h(v[0].x), u2h(v[8].x));
        __half2 p1a = __hadd2(u2h(v[1].x), u2h(v[7].x));
        __half2 p2a = __hadd2(u2h(v[2].x), u2h(v[6].x));
        __half2 p3a = __hadd2(u2h(v[3].x), u2h(v[5].x));
        __half2 b0  = __hmul2(u2h(c_gh2[4]), u2h(v[4].x));
        b0 = __hfma2(u2h(c_gh2[0]), p0a, b0);
        b0 = __hfma2(u2h(c_gh2[1]), p1a, b0);
        b0 = __hfma2(u2h(c_gh2[2]), p2a, b0);
        b0 = __hfma2(u2h(c_gh2[3]), p3a, b0);

        __half2 p0b = __hadd2(u2h(v[0].y), u2h(v[8].y));
        __half2 p1b = __hadd2(u2h(v[1].y), u2h(v[7].y));
        __half2 p2b = __hadd2(u2h(v[2].y), u2h(v[6].y));
        __half2 p3b = __hadd2(u2h(v[3].y), u2h(v[5].y));
        __half2 b1  = __hmul2(u2h(c_gh2[4]), u2h(v[4].y));
        b1 = __hfma2(u2h(c_gh2[0]), p0b, b1);
        b1 = __hfma2(u2h(c_gh2[1]), p1b, b1);
        b1 = __hfma2(u2h(c_gh2[2]), p2b, b1);
        b1 = __hfma2(u2h(c_gh2[3]), p3b, b1);

        float2 f0 = __half22float2(b0);
        float2 f1 = __half22float2(b1);

        float4 lab = __ldcs(lp + (size_t)z * (HW/4));
        float4 inp = ip[(size_t)z * (HW/4)];

        {
            float d = inp.x - mean, d2 = d*d, wv = __expf(-d2*d2);
            num = fmaf(f0.x * lab.x, wv, num); den = fmaf(f0.x, wv, den);
        }
        {
            float d = inp.y - mean, d2 = d*d, wv = __expf(-d2*d2);
            num = fmaf(f0.y * lab.y, wv, num); den = fmaf(f0.y, wv, den);
        }
        {
            float d = inp.z - mean, d2 = d*d, wv = __expf(-d2*d2);
            num = fmaf(f1.x * lab.z, wv, num); den = fmaf(f1.x, wv, den);
        }
        {
            float d = inp.w - mean, d2 = d*d, wv = __expf(-d2*d2);
            num = fmaf(f1.y * lab.w, wv, num); den = fmaf(f1.y, wv, den);
        }

        #pragma unroll
        for (int j = 0; j < 8; j++) v[j] = v[j + 1];
        int zn = z + RAD + 1;
        v[8] = (zn < DIMZ)
             ? *reinterpret_cast<const uint2*>(bp + (size_t)zn * HW)
             : make_uint2(0u, 0u);
    }

    // CTA reduction -> 2 double atomics.
    #pragma unroll
    for (int o = 16; o; o >>= 1) {
        num += __shfl_down_sync(0xffffffffu, num, o);
        den += __shfl_down_sync(0xffffffffu, den, o);
    }
    __shared__ float rn[8], rd[8];
    if (lane == 0) { rn[warp] = num; rd[warp] = den; }
    __syncthreads();
    __shared__ bool is_last;
    if (tid == 0) {
        double a = 0.0, c = 0.0;
        #pragma unroll
        for (int w = 0; w < 8; w++) { a += (double)rn[w]; c += (double)rd[w]; }
        atomicAdd(&g_s.num[k], a);
        atomicAdd(&g_s.den[k], c);
        __threadfence();
        int done = atomicAdd(&g_s.ctr, 1);
        is_last = (done == K2_CTAS - 1);
    }
    __syncthreads();

    if (is_last && tid == 0) {
        __threadfence();
        float loss = 0.f;
        #pragma unroll
        for (int kk = 0; kk < NK; kk++) {
            float n = (float)g_s.num[kk];
            float d = (float)g_s.den[kk];
            loss += fabsf(n / (d + 1e-6f));
        }
        out[0] = (float)NK - loss;
    }
}

extern "C" void kernel_launch(void* const* d_in, const int* in_sizes, int n_in,
                              void* d_out, int out_size) {
    const float* labels;
    const float* inputs;
    if (in_sizes[0] == NB*NK*VOL) {
        labels = (const float*)d_in[0];
        inputs = (const float*)d_in[1];
    } else {
        labels = (const float*)d_in[1];
        inputs = (const float*)d_in[0];
    }

    void* scal_ptr = nullptr;
    cudaGetSymbolAddress(&scal_ptr, g_s);
    cudaMemsetAsync(scal_ptr, 0, sizeof(Scal));

    dim3 g1(64, 4, 2);
    k_xyblur<<<g1, 256>>>(labels, inputs);

    dim3 g2(16, 8, 8);
    k_zred<<<g2, 256>>>(labels, inputs, (float*)d_out);
}